// round 3
// baseline (speedup 1.0000x reference)
#include <cuda_runtime.h>
#include <cuda_bf16.h>

// Problem constants (fixed by the problem spec)
#define NS        4096
#define NQ_TOTAL  32768     // B * N_Q
#define KNN       8
#define FDIM      256
#define FDIM4     (FDIM/4)

#define HALF_NS   2048      // sensors per lane (2-way lane split per query)
#define QPB       128       // queries per block (256 threads = 128 queries x 2 halves)
#define CAP       40        // candidate buffer capacity (local mem)
#define CAPCHK    32        // fold trigger (CAP - 8 headroom per unrolled body)

// Inter-kernel scratch (device globals: allowed; no allocation)
__device__ float g_w  [NQ_TOTAL * KNN];
__device__ int   g_idx[NQ_TOTAL * KNN];

// Unconditional branchless sorted insert of (x, xi) into a descending
// (value, idx) top-8 list. If x <= v[7] the list is unchanged.
// Strict '>' keeps earlier (lower-index) entries on exact ties (stable).
__device__ __forceinline__ void pair_insert(float x, int xi,
                                            float (&v)[KNN], int (&ii)[KNN])
{
#pragma unroll
    for (int j = KNN - 1; j >= 1; --j) {   // descending: v[j-1] still old
        bool pjm = x > v[j-1];
        bool pj  = x > v[j];
        v[j]  = pjm ? v[j-1]  : (pj ? x  : v[j]);
        ii[j] = pjm ? ii[j-1] : (pj ? xi : ii[j]);
    }
    bool p0 = x > v[0];
    v[0]  = p0 ? x  : v[0];
    ii[0] = p0 ? xi : ii[0];
}

// ---------------------------------------------------------------------------
// Scan kernel: exact top-8 per query by score t = q.s - 0.5|s|^2 (max == nearest).
// Thread = (query, half). Hot loop is branch-free: unconditional buffered store,
// cursor advances only on t > thr. Warp-uniform fold merges buffer into the
// register top-8 and tightens thr.
// ---------------------------------------------------------------------------
__global__ void __launch_bounds__(256) scan_kernel(const float* __restrict__ qc,
                                                   const float* __restrict__ sc)
{
    extern __shared__ float4 sh[];                    // NS float4 = 64 KB
    float2* mscr = reinterpret_cast<float2*>(sh + NS); // 128*8 float2 = 8 KB

    const int tid = threadIdx.x;

    // Stage + preprocess sensor coords (x, y, z, 0.5*|s|^2)
    for (int i = tid; i < NS; i += 256) {
        float sx = sc[3*i+0], sy = sc[3*i+1], sz = sc[3*i+2];
        sh[i] = make_float4(sx, sy, sz, 0.5f * (sx*sx + sy*sy + sz*sz));
    }
    __syncthreads();

    const int ql   = tid & (QPB - 1);
    const int half = tid >> 7;                 // warps 0-3: half 0, warps 4-7: half 1
    const int q    = blockIdx.x * QPB + ql;

    const float qx = qc[3*q+0];
    const float qy = qc[3*q+1];
    const float qz = qc[3*q+2];

    float v[KNN]; int ii[KNN];
#pragma unroll
    for (int j = 0; j < KNN; j++) { v[j] = -3.0e38f; ii[j] = 0; }

    float  thr = -3.0e38f;          // current 8th best (tightens at folds)
    float2 buf[CAP];                // local-memory candidate buffer
    int    cnt = 0;

    const int base = half * HALF_NS;

    for (int s0 = 0; s0 < HALF_NS; s0 += 8) {
#pragma unroll
        for (int u = 0; u < 8; u++) {
            const int s = base + s0 + u;
            float4 h = sh[s];
            float  t = fmaf(qx, h.x, fmaf(qy, h.y, fmaf(qz, h.z, -h.w)));
            buf[cnt] = make_float2(t, __int_as_float(s));  // unconditional store
            cnt += (t > thr);                              // advance only on hit
        }
        // warp-uniform fold check (entering body cnt <= 31 -> max write idx 38)
        if (__any_sync(0xffffffffu, cnt >= CAPCHK)) {
            for (int j = 0; j < cnt; j++)
                pair_insert(buf[j].x, __float_as_int(buf[j].y), v, ii);
            cnt = 0;
            thr = v[KNN-1];
        }
    }
    // final fold
    for (int j = 0; j < cnt; j++)
        pair_insert(buf[j].x, __float_as_int(buf[j].y), v, ii);

    // Merge halves through shared scratch: half 1 publishes, half 0 folds.
    if (half == 1) {
#pragma unroll
        for (int j = 0; j < KNN; j++)
            mscr[ql * KNN + j] = make_float2(v[j], __int_as_float(ii[j]));
    }
    __syncthreads();

    if (half == 0) {
#pragma unroll
        for (int j = 0; j < KNN; j++) {
            float2 e = mscr[ql * KNN + j];
            pair_insert(e.x, __float_as_int(e.y), v, ii);
        }

        // Exact distances for the 8 winners (no cancellation), IDW weights
        float w[KNN];
        float wsum = 0.0f;
#pragma unroll
        for (int j = 0; j < KNN; j++) {
            float4 h  = sh[ii[j]];
            float dx = qx - h.x, dy = qy - h.y, dz = qz - h.z;
            float d2 = fmaf(dx, dx, fmaf(dy, dy, dz*dz));
            float d  = sqrtf(d2);
            float wj = 1.0f / (d + 1e-8f);
            w[j] = wj;
            wsum += wj;
        }
        const float inv = 1.0f / wsum;
#pragma unroll
        for (int j = 0; j < KNN; j++) {
            g_w  [q*KNN + j] = w[j] * inv;
            g_idx[q*KNN + j] = ii[j];
        }
    }
}

// ---------------------------------------------------------------------------
// Gather kernel: weighted feature gather. One warp per query, coalesced float4.
// ---------------------------------------------------------------------------
__global__ void __launch_bounds__(256) gather_kernel(const float* __restrict__ feats,
                                                     float* __restrict__ out)
{
    const int gw   = (blockIdx.x * 256 + threadIdx.x) >> 5;  // global query id
    const int lane = threadIdx.x & 31;
    const int b    = gw >> 13;                               // / 8192

    const float4* __restrict__ fb =
        reinterpret_cast<const float4*>(feats) + (size_t)b * NS * FDIM4;

    float4 a0 = make_float4(0.f, 0.f, 0.f, 0.f);
    float4 a1 = make_float4(0.f, 0.f, 0.f, 0.f);

#pragma unroll
    for (int k = 0; k < KNN; k++) {
        const float wk = g_w  [gw*KNN + k];   // same addr across warp -> broadcast
        const int   id = g_idx[gw*KNN + k];
        const float4* __restrict__ fr = fb + (size_t)id * FDIM4;
        float4 f0 = fr[lane];
        float4 f1 = fr[lane + 32];
        a0.x = fmaf(wk, f0.x, a0.x); a0.y = fmaf(wk, f0.y, a0.y);
        a0.z = fmaf(wk, f0.z, a0.z); a0.w = fmaf(wk, f0.w, a0.w);
        a1.x = fmaf(wk, f1.x, a1.x); a1.y = fmaf(wk, f1.y, a1.y);
        a1.z = fmaf(wk, f1.z, a1.z); a1.w = fmaf(wk, f1.w, a1.w);
    }

    float4* __restrict__ o = reinterpret_cast<float4*>(out) + (size_t)gw * FDIM4;
    o[lane]      = a0;
    o[lane + 32] = a1;
}

// ---------------------------------------------------------------------------
// Launch: two dependent kernels, graph-capturable, allocation-free.
// ---------------------------------------------------------------------------
extern "C" void kernel_launch(void* const* d_in, const int* in_sizes, int n_in,
                              void* d_out, int out_size)
{
    const float* qc = (const float*)d_in[0];   // query_coords   (B, NQ, 3)
    const float* sc = (const float*)d_in[1];   // sensor_coords  (NS, 3)
    const float* ft = (const float*)d_in[2];   // sensor_features(B, NS, F)

    const int smem = NS * 16 + QPB * KNN * 8;  // 64 KB tile + 8 KB merge scratch

    cudaFuncSetAttribute(scan_kernel,
                         cudaFuncAttributeMaxDynamicSharedMemorySize, smem);

    scan_kernel<<<NQ_TOTAL / QPB, 256, smem>>>(qc, sc);
    gather_kernel<<<(NQ_TOTAL * 32) / 256, 256>>>(ft, (float*)d_out);
}

// round 4
// speedup vs baseline: 7.5195x; 7.5195x over previous
#include <cuda_runtime.h>
#include <cuda_bf16.h>

// Problem constants (fixed by the problem spec)
#define NS        4096
#define HALF_NS   2048
#define NQ_TOTAL  32768     // B * N_Q
#define KNN       8
#define FDIM      256
#define FDIM4     (FDIM/4)

#define THREADS   256       // scan: threads per block = queries per block
#define GROUP     16        // sensors per branch-free group
#define BUF_DEPTH 32        // smem candidate buffer depth per thread
#define FOLD_TRIG 16        // fold when any lane's cnt >= this (headroom = GROUP)

// Inter-kernel scratch (device globals: allowed; no allocation)
__device__ float2 g_part[2 * KNN * NQ_TOTAL];   // [half][j][q] partial top-8, 4 MB
__device__ float  g_w  [NQ_TOTAL * KNN];
__device__ int    g_idx[NQ_TOTAL * KNN];

// Branchless sorted insert of (x, xi) into descending (value, idx) top-8 list.
// Strict '>' keeps earlier entries on exact ties (matches jax top_k first-index).
__device__ __forceinline__ void pair_insert(float x, int xi,
                                            float (&v)[KNN], int (&ii)[KNN])
{
#pragma unroll
    for (int j = KNN - 1; j >= 1; --j) {   // v[j-1] still old value here
        bool pjm = x > v[j-1];
        bool pj  = x > v[j];
        v[j]  = pjm ? v[j-1]  : (pj ? x  : v[j]);
        ii[j] = pjm ? ii[j-1] : (pj ? xi : ii[j]);
    }
    bool p0 = x > v[0];
    v[0]  = p0 ? x  : v[0];
    ii[0] = p0 ? xi : ii[0];
}

// ---------------------------------------------------------------------------
// Scan kernel. Block = (query group of 256) x (sensor half of 2048).
// Score t = q.s - 0.5|s|^2; max-t == nearest. Hot loop is branch-free:
// unconditional STS of the candidate into a per-thread SMEM column, cursor
// advances only on t > thr. Warp-uniform folds merge buffered candidates into
// the register-resident sorted top-8 and tighten thr.
// ---------------------------------------------------------------------------
__global__ void __launch_bounds__(THREADS) scan_kernel(const float* __restrict__ qc,
                                                       const float* __restrict__ sc)
{
    extern __shared__ float4 tile[];                         // HALF_NS * 16B = 32 KB
    float2* buf = reinterpret_cast<float2*>(tile + HALF_NS); // [BUF_DEPTH][THREADS] = 64 KB

    const int tid   = threadIdx.x;
    const int half  = blockIdx.x & 1;
    const int sbase = half * HALF_NS;
    const int q     = (blockIdx.x >> 1) * THREADS + tid;

    // Stage + preprocess this half's sensors: (x, y, z, 0.5*|s|^2)
    for (int i = tid; i < HALF_NS; i += THREADS) {
        const int s = sbase + i;
        float sx = sc[3*s+0], sy = sc[3*s+1], sz = sc[3*s+2];
        tile[i] = make_float4(sx, sy, sz, 0.5f * (sx*sx + sy*sy + sz*sz));
    }
    __syncthreads();

    const float qx = qc[3*q+0];
    const float qy = qc[3*q+1];
    const float qz = qc[3*q+2];

    float v[KNN]; int ii[KNN];
#pragma unroll
    for (int j = 0; j < KNN; j++) { v[j] = -3.0e38f; ii[j] = 0; }

    float thr = -3.0e38f;
    int   cnt = 0;

    for (int s0 = 0; s0 < HALF_NS; s0 += GROUP) {
#pragma unroll
        for (int u = 0; u < GROUP; u++) {
            float4 h = tile[s0 + u];
            float  t = fmaf(qx, h.x, fmaf(qy, h.y, fmaf(qz, h.z, -h.w)));
            buf[cnt * THREADS + tid] =
                make_float2(t, __int_as_float(sbase + s0 + u));  // unconditional STS
            cnt += (t > thr);                                    // predicated bump
        }
        // warp-uniform fold (entering body cnt <= 15 -> max write index 30 < 32)
        if (__any_sync(0xffffffffu, cnt >= FOLD_TRIG)) {
            for (int j = 0; j < cnt; j++) {
                float2 e = buf[j * THREADS + tid];
                pair_insert(e.x, __float_as_int(e.y), v, ii);
            }
            cnt = 0;
            thr = v[KNN-1];
        }
    }
    // final drain
    for (int j = 0; j < cnt; j++) {
        float2 e = buf[j * THREADS + tid];
        pair_insert(e.x, __float_as_int(e.y), v, ii);
    }

    // Publish sorted partial top-8, coalesced [half][j][q] layout
#pragma unroll
    for (int j = 0; j < KNN; j++)
        g_part[(half * KNN + j) * NQ_TOTAL + q] =
            make_float2(v[j], __int_as_float(ii[j]));
}

// ---------------------------------------------------------------------------
// Finalize: merge the two sorted halves, exact distances (no cancellation),
// IDW weights. One thread per query.
// ---------------------------------------------------------------------------
__global__ void __launch_bounds__(256) finalize_kernel(const float* __restrict__ qc,
                                                       const float* __restrict__ sc)
{
    const int q = blockIdx.x * 256 + threadIdx.x;

    float v[KNN]; int ii[KNN];
#pragma unroll
    for (int j = 0; j < KNN; j++) {            // half 0 list is already sorted desc
        float2 e = g_part[j * NQ_TOTAL + q];
        v[j]  = e.x;
        ii[j] = __float_as_int(e.y);
    }
#pragma unroll
    for (int j = 0; j < KNN; j++) {            // fold in half 1
        float2 e = g_part[(KNN + j) * NQ_TOTAL + q];
        pair_insert(e.x, __float_as_int(e.y), v, ii);
    }

    const float qx = qc[3*q+0];
    const float qy = qc[3*q+1];
    const float qz = qc[3*q+2];

    float w[KNN];
    float wsum = 0.0f;
#pragma unroll
    for (int j = 0; j < KNN; j++) {
        const int s = ii[j];
        float dx = qx - sc[3*s+0];
        float dy = qy - sc[3*s+1];
        float dz = qz - sc[3*s+2];
        float d  = sqrtf(fmaf(dx, dx, fmaf(dy, dy, dz*dz)));
        float wj = 1.0f / (d + 1e-8f);
        w[j] = wj;
        wsum += wj;
    }
    const float inv = 1.0f / wsum;
#pragma unroll
    for (int j = 0; j < KNN; j++) {
        g_w  [q*KNN + j] = w[j] * inv;
        g_idx[q*KNN + j] = ii[j];
    }
}

// ---------------------------------------------------------------------------
// Gather kernel: weighted feature gather. One warp per query, coalesced float4.
// ---------------------------------------------------------------------------
__global__ void __launch_bounds__(256) gather_kernel(const float* __restrict__ feats,
                                                     float* __restrict__ out)
{
    const int gw   = (blockIdx.x * 256 + threadIdx.x) >> 5;  // global query id
    const int lane = threadIdx.x & 31;
    const int b    = gw >> 13;                               // / 8192

    const float4* __restrict__ fb =
        reinterpret_cast<const float4*>(feats) + (size_t)b * NS * FDIM4;

    float4 a0 = make_float4(0.f, 0.f, 0.f, 0.f);
    float4 a1 = make_float4(0.f, 0.f, 0.f, 0.f);

#pragma unroll
    for (int k = 0; k < KNN; k++) {
        const float wk = g_w  [gw*KNN + k];   // same addr across warp -> broadcast
        const int   id = g_idx[gw*KNN + k];
        const float4* __restrict__ fr = fb + (size_t)id * FDIM4;
        float4 f0 = fr[lane];
        float4 f1 = fr[lane + 32];
        a0.x = fmaf(wk, f0.x, a0.x); a0.y = fmaf(wk, f0.y, a0.y);
        a0.z = fmaf(wk, f0.z, a0.z); a0.w = fmaf(wk, f0.w, a0.w);
        a1.x = fmaf(wk, f1.x, a1.x); a1.y = fmaf(wk, f1.y, a1.y);
        a1.z = fmaf(wk, f1.z, a1.z); a1.w = fmaf(wk, f1.w, a1.w);
    }

    float4* __restrict__ o = reinterpret_cast<float4*>(out) + (size_t)gw * FDIM4;
    o[lane]      = a0;
    o[lane + 32] = a1;
}

// ---------------------------------------------------------------------------
// Launch: three dependent kernels, graph-capturable, allocation-free.
// ---------------------------------------------------------------------------
extern "C" void kernel_launch(void* const* d_in, const int* in_sizes, int n_in,
                              void* d_out, int out_size)
{
    const float* qc = (const float*)d_in[0];   // query_coords   (B, NQ, 3)
    const float* sc = (const float*)d_in[1];   // sensor_coords  (NS, 3)
    const float* ft = (const float*)d_in[2];   // sensor_features(B, NS, F)

    const int smem = HALF_NS * 16 + BUF_DEPTH * THREADS * 8;  // 32 KB + 64 KB

    cudaFuncSetAttribute(scan_kernel,
                         cudaFuncAttributeMaxDynamicSharedMemorySize, smem);

    scan_kernel    <<<(NQ_TOTAL / THREADS) * 2, THREADS, smem>>>(qc, sc);
    finalize_kernel<<< NQ_TOTAL / 256, 256>>>(qc, sc);
    gather_kernel  <<<(NQ_TOTAL * 32) / 256, 256>>>(ft, (float*)d_out);
}